// round 6
// baseline (speedup 1.0000x reference)
#include <cuda_runtime.h>
#include <math.h>

#define Bn 64
#define Pn 64
#define Nn 1000
#define Hn 128
typedef unsigned long long ull;

__device__ float g_fq[Bn * Pn * Hn];   // only scratch: final_q (2MB)

__device__ __forceinline__ void ffma2(ull &d, ull a, ull b) {
    asm("fma.rn.f32x2 %0, %1, %2, %0;" : "+l"(d) : "l"(a), "l"(b));
}
__device__ __forceinline__ void fadd2(ull &d, ull a) {
    asm("add.rn.f32x2 %0, %1, %0;" : "+l"(d) : "l"(a));
}
__device__ __forceinline__ ull dup2(float x) {
    ull r; asm("mov.b64 %0, {%1, %1};" : "=l"(r) : "f"(x)); return r;
}
__device__ __forceinline__ float2 unpk(ull v) {
    float2 f; asm("mov.b64 {%0, %1}, %2;" : "=f"(f.x), "=f"(f.y) : "l"(v)); return f;
}

// ============ Kernel 1: fused prep. grid=256, block=512 ============
__global__ __launch_bounds__(512) void k_prep(
    const float* __restrict__ emb, const float* __restrict__ encq1,
    const int* __restrict__ lastn, const float* __restrict__ loadv,
    const float* __restrict__ gmask,
    const float* __restrict__ Wg, const float* __restrict__ Wf,
    const float* __restrict__ Wl, const float* __restrict__ Wv,
    const float* __restrict__ Wload, const float* __restrict__ bload)
{
    const int b = blockIdx.x >> 2, p0 = (blockIdx.x & 3) * 16;
    const int tx = threadIdx.x, gid = tx >> 7, t = tx & 127;
    const int pr = t >> 5, hc = t & 31;          // pr warp-uniform
    __shared__ __align__(16) float SB[10880];

    // Phase A: masked aggregation over n-range [gid*250, +250)
    float* Es = SB + gid * 2304;                 // [16][128]
    float* mt = Es + 2048;                       // [16][16]
    ull acc[4][2] = {{0,0},{0,0},{0,0},{0,0}}, cs0 = 0, cs1 = 0;
    const int nbeg = gid * 250, mk = t & 15, mp = t >> 4;

    for (int c = 0; c < 16; c++) {
        const int n0 = nbeg + c * 16;
        const int kt = min(16, nbeg + 250 - n0);
        const float4* eb = (const float4*)(emb + (size_t)(b * Nn + n0) * Hn);
        for (int id = t; id < kt * 32; id += 128) ((float4*)Es)[id] = eb[id];
        if (mk < kt) {
#pragma unroll
            for (int s = 0; s < 2; s++) {
                int p = mp + 8 * s;
                float v = gmask[(size_t)(b * Pn + p0 + p) * Nn + n0 + mk];
                mt[mk * 16 + p] = (__float_as_uint(v) == 0xff800000u) ? 1.0f : v;
            }
        }
        __syncthreads();
#pragma unroll 2
        for (int k = 0; k < kt; k++) {
            const ull* ev = (const ull*)(Es + k * 128 + 4 * hc);
            ull e0 = ev[0], e1 = ev[1];
            float4 mq = *(const float4*)(mt + k * 16 + 4 * pr);
            ull m;
            m = dup2(mq.x); ffma2(acc[0][0], m, e0); ffma2(acc[0][1], m, e1);
            m = dup2(mq.y); ffma2(acc[1][0], m, e0); ffma2(acc[1][1], m, e1);
            m = dup2(mq.z); ffma2(acc[2][0], m, e0); ffma2(acc[2][1], m, e1);
            m = dup2(mq.w); ffma2(acc[3][0], m, e0); ffma2(acc[3][1], m, e1);
            if (pr == 0) { fadd2(cs0, e0); fadd2(cs1, e1); }
        }
        __syncthreads();
    }

    // dump partials [4g][16p][128h] at 0, csum [4g][128h] at 8192
    {
        float* Pp = SB + (size_t)(gid * 16 + 4 * pr) * 128 + 4 * hc;
#pragma unroll
        for (int pi = 0; pi < 4; pi++) {
            ((ull*)(Pp + pi * 128))[0] = acc[pi][0];
            ((ull*)(Pp + pi * 128))[1] = acc[pi][1];
        }
        if (pr == 0) {
            ull* cp = (ull*)(SB + 8192 + gid * 128 + 4 * hc);
            cp[0] = cs0; cp[1] = cs1;
        }
    }
    __syncthreads();

    const float invN = 1.0f / Nn;
    const int pl = tx & 15, h0 = (tx >> 4) * 4;
    float r[4] = {0, 0, 0, 0}, cz = 0.f;
#pragma unroll
    for (int g = 0; g < 4; g++) {
        float4 s = *(const float4*)(SB + (size_t)(g * 16 + pl) * 128 + h0);
        r[0] += s.x; r[1] += s.y; r[2] += s.z; r[3] += s.w;
    }
    if (tx < 128) cz = SB[8192+tx] + SB[8320+tx] + SB[8448+tx] + SB[8576+tx];
    __syncthreads();
    // aggT [h][16p] at 8704, meanv at 10752; stage eq1T at 0, lastT at 2048
#pragma unroll
    for (int i = 0; i < 4; i++) SB[8704 + (h0 + i) * 16 + pl] = r[i] * invN;
    if (tx < 128) SB[10752 + tx] = cz * invN;
#pragma unroll
    for (int j = 0; j < 4; j++) {
        int p = 4 * gid + j;
        SB[t * 16 + p] = encq1[(size_t)(b * Pn + p0 + p) * Hn + t];
        int ln = lastn[b * Pn + p0 + p];
        SB[2048 + t * 16 + p] = emb[(size_t)(b * Nn + ln) * Hn + t];
    }
    __syncthreads();

    // projections: group 0:Wf*eq1T  1:Wl*lastT  2:Wv*aggT  3:qg
    ull pa[8] = {0,0,0,0,0,0,0,0};
    float qg = 0.f;
    if (gid < 3) {
        const float* opT = (gid == 0) ? SB : (gid == 1) ? SB + 2048 : SB + 8704;
        const float* Wm  = (gid == 0) ? Wf : (gid == 1) ? Wl : Wv;
#pragma unroll 2
        for (int k = 0; k < 128; k++) {
            ull w2 = dup2(Wm[k * 128 + t]);
            const ull* op = (const ull*)(opT + k * 16);
#pragma unroll
            for (int j = 0; j < 8; j++) ffma2(pa[j], w2, op[j]);
        }
    } else {
        const float* mv = SB + 10752;
#pragma unroll 4
        for (int k = 0; k < 128; k++) qg = fmaf(mv[k], Wg[k * 128 + t], qg);
    }
    __syncthreads();
    if (gid < 3) {
        float* R = SB + gid * 2048;                  // [16p][128h]
#pragma unroll
        for (int j = 0; j < 8; j++) {
            float2 f = unpk(pa[j]);
            R[(2 * j) * 128 + t] = f.x;
            R[(2 * j + 1) * 128 + t] = f.y;
        }
    } else SB[6144 + t] = qg;
    __syncthreads();

    // combine -> g_fq
    {
        const int h = tx & 127, pp = tx >> 7;
        const float wl_h = Wload[h], bl = bload[h], qgh = SB[6144 + h];
#pragma unroll
        for (int j = 0; j < 4; j++) {
            int p = 4 * pp + j;
            g_fq[(size_t)(b * Pn + p0 + p) * Hn + h] =
                SB[p * 128 + h] + SB[2048 + p * 128 + h] + SB[4096 + p * 128 + h]
                + qgh + bl + loadv[b * Pn + p0 + p] * wl_h;
        }
    }
}

// ============ Kernel 2: score, fq in registers. grid=1024, block=128 ====
__global__ __launch_bounds__(128) void k_score(
    const float* __restrict__ dists, const float* __restrict__ emb,
    const int* __restrict__ lastn, const float* __restrict__ gmask,
    float* __restrict__ out)
{
    const int sc = blockIdx.x & 3, pt = (blockIdx.x >> 2) & 3, b = blockIdx.x >> 4;
    const int p0 = pt * 16, tx = threadIdx.x, w = tx >> 5, li = tx & 31;
    const int hs = li >> 2, nj = li & 3;       // h-slice 0..7, n-sub 0..3

    __shared__ __align__(16) float Es[64 * 132];
    __shared__ int lns[16];

    ull fq[4][8];
#pragma unroll
    for (int pi = 0; pi < 4; pi++) {
        const float* src = g_fq + (size_t)(b * Pn + p0 + 4 * w + pi) * Hn + hs * 16;
#pragma unroll
        for (int j = 0; j < 8; j++) fq[pi][j] = *(const ull*)(src + 2 * j);
    }
    if (tx < 16) lns[tx] = lastn[b * Pn + p0 + tx];

    const int nbeg = sc * 250;
    const float* dbase = dists + (size_t)b * Nn * Nn;

    for (int ch = 0; ch < 4; ch++) {
        const int n0 = nbeg + ch * 64;
        const int nt = min(64, nbeg + 250 - n0);
        const float4* eb = (const float4*)(emb + (size_t)(b * Nn + n0) * Hn);
        __syncthreads();
        for (int id = tx; id < nt * 32; id += 128) {
            int rr = id >> 5, cc = id & 31;
            *(float4*)(Es + rr * 132 + 4 * cc) = eb[id];
        }
        __syncthreads();

        const int steps = (nt + 3) >> 2;
        for (int s = 0; s < steps; s++) {
            const int nl = s * 4 + nj;
            const ull* ep = (const ull*)(Es + nl * 132 + hs * 16);
            ull acc[4] = {0, 0, 0, 0};
#pragma unroll
            for (int j = 0; j < 8; j++) {
                ull e = ep[j];
                ffma2(acc[0], fq[0][j], e);
                ffma2(acc[1], fq[1][j], e);
                ffma2(acc[2], fq[2][j], e);
                ffma2(acc[3], fq[3][j], e);
            }
            float sv[4];
#pragma unroll
            for (int pi = 0; pi < 4; pi++) { float2 f = unpk(acc[pi]); sv[pi] = f.x + f.y; }
#pragma unroll
            for (int o = 4; o < 32; o <<= 1)
#pragma unroll
                for (int pi = 0; pi < 4; pi++)
                    sv[pi] += __shfl_xor_sync(0xffffffffu, sv[pi], o);

            if (hs < 4 && nl < nt) {
                float s_ = (hs == 0) ? sv[0] : (hs == 1) ? sv[1] : (hs == 2) ? sv[2] : sv[3];
                const int p = p0 + 4 * w + hs, n = n0 + nl;
                float d = dbase[(size_t)lns[4 * w + hs] * Nn + n];
                float tt = 10.0f * tanhf(s_ * 0.08838834764831845f
                                         - d * 0.7071067811865476f);
                float mv = gmask[(size_t)(b * Pn + p) * Nn + n];
                tt += (__float_as_uint(mv) == 0xff800000u) ? -1e8f : mv;
                out[(size_t)(b * Pn + p) * Nn + n] = tt;
            }
        }
    }
}

// ============ Kernel 3: row softmax ============
__global__ __launch_bounds__(256) void k_softmax(float* __restrict__ out) {
    __shared__ float buf[Nn];
    __shared__ float red[33];
    const int tx = threadIdx.x;
    float* r = out + (size_t)blockIdx.x * Nn;
    float mx = -3.4e38f;
    for (int i = tx; i < Nn; i += 256) { float v = r[i]; buf[i] = v; mx = fmaxf(mx, v); }
#pragma unroll
    for (int o = 16; o > 0; o >>= 1) mx = fmaxf(mx, __shfl_xor_sync(0xffffffffu, mx, o));
    if ((tx & 31) == 0) red[tx >> 5] = mx;
    __syncthreads();
    if (tx == 0) { float m = red[0]; for (int w = 1; w < 8; w++) m = fmaxf(m, red[w]); red[32] = m; }
    __syncthreads();
    mx = red[32];
    float s = 0.f;
    for (int i = tx; i < Nn; i += 256) { float e = __expf(buf[i] - mx); buf[i] = e; s += e; }
#pragma unroll
    for (int o = 16; o > 0; o >>= 1) s += __shfl_xor_sync(0xffffffffu, s, o);
    if ((tx & 31) == 0) red[tx >> 5] = s;
    __syncthreads();
    if (tx == 0) { float tsum = 0.f; for (int w = 0; w < 8; w++) tsum += red[w]; red[32] = 1.0f / tsum; }
    __syncthreads();
    const float inv = red[32];
    for (int i = tx; i < Nn; i += 256) r[i] = buf[i] * inv;
}

extern "C" void kernel_launch(void* const* d_in, const int* in_sizes, int n_in,
                              void* d_out, int out_size) {
    (void)in_sizes; (void)n_in; (void)out_size;
    const float* dists = (const float*)d_in[0];
    const float* emb   = (const float*)d_in[1];
    const float* encq1 = (const float*)d_in[2];
    const int*   lastn = (const int*)d_in[3];
    const float* loadv = (const float*)d_in[4];
    const float* gmask = (const float*)d_in[5];
    const float* Wg = (const float*)d_in[6];
    const float* Wf = (const float*)d_in[7];
    const float* Wl = (const float*)d_in[8];
    const float* Wv = (const float*)d_in[9];
    const float* Wload = (const float*)d_in[10];
    const float* bload = (const float*)d_in[11];
    float* out = (float*)d_out;

    k_prep<<<256, 512>>>(emb, encq1, lastn, loadv, gmask, Wg, Wf, Wl, Wv, Wload, bload);
    k_score<<<1024, 128>>>(dists, emb, lastn, gmask, out);
    k_softmax<<<Bn * Pn, 256>>>(out);
}